// round 1
// baseline (speedup 1.0000x reference)
#include <cuda_runtime.h>

// TRFAligner: out[d, t] = sum over (seq, k) with sourceIdx[seq] + k == t of TRFs[seq, k, d]
// TRFs: (nSeq, nWin, OUTD) fp32 row-major; out: (OUTD, nRealLen) fp32 row-major.
// sourceIdx is sorted ascending -> tile the timeline, gather via binary search,
// accumulate in shared memory (no atomics anywhere).

#define OUTD     128
#define TILE_T   64
#define ROWPAD   4
#define ROWSTRIDE (OUTD + ROWPAD)   // 132 floats; mult of 4 -> float4 aligned
#define NWARPS   8
#define NTHREADS (NWARPS * 32)

__global__ __launch_bounds__(NTHREADS) void trf_fold_kernel(
    const float* __restrict__ TRFs,
    const int*   __restrict__ sIdx,
    float*       __restrict__ out,
    int nSeq, int nWin, int nRealLen)
{
    __shared__ float sm[TILE_T * ROWSTRIDE];

    const int t0      = blockIdx.x * TILE_T;
    const int tEnd    = min(t0 + TILE_T, nRealLen);
    const int tileLen = tEnd - t0;
    const int tid     = threadIdx.x;

    // ---- zero accumulator tile ----
    #pragma unroll
    for (int i = tid; i < TILE_T * ROWSTRIDE; i += NTHREADS) sm[i] = 0.0f;
    __syncthreads();

    // ---- binary search the seq range overlapping this tile ----
    // need seqs with sIdx in [t0 - nWin + 1, tEnd - 1]
    int seqLo, seqHi;
    {
        int lo = 0, hi = nSeq, thr = t0 - nWin + 1;
        while (lo < hi) { int m = (lo + hi) >> 1; if (sIdx[m] < thr) lo = m + 1; else hi = m; }
        seqLo = lo;
        hi = nSeq;
        while (lo < hi) { int m = (lo + hi) >> 1; if (sIdx[m] < tEnd) lo = m + 1; else hi = m; }
        seqHi = lo;
    }

    const int w    = tid >> 5;   // warp id: owns tt rows with (tt % 8) == w -> no cross-warp RMW
    const int lane = tid & 31;   // lane covers d = 4*lane .. 4*lane+3 via float4

    // ---- accumulate ----
    for (int i = seqLo; i < seqHi; ++i) {
        const int s   = sIdx[i];
        const int rlo = max(t0, s) - t0;
        const int rhi = min(tEnd - 1, s + nWin - 1) - t0;
        int tt = rlo + ((w - rlo) & (NWARPS - 1));   // first owned row >= rlo
        const float4* __restrict__ src =
            reinterpret_cast<const float4*>(TRFs + (size_t)i * nWin * OUTD);
        for (; tt <= rhi; tt += NWARPS) {
            const int k = t0 + tt - s;               // 0 <= k < nWin by construction
            float4 v = src[k * (OUTD / 4) + lane];   // coalesced 512B row read
            float* ap = sm + tt * ROWSTRIDE + lane * 4;
            float4 a = *reinterpret_cast<float4*>(ap);
            a.x += v.x; a.y += v.y; a.z += v.z; a.w += v.w;
            *reinterpret_cast<float4*>(ap) = a;      // conflict-free: lanes span all banks
        }
    }
    __syncthreads();

    // ---- write out (exclusive tile ownership -> plain stores, coalesced over t) ----
    for (int idx = tid; idx < OUTD * TILE_T; idx += NTHREADS) {
        const int d  = idx / TILE_T;
        const int tt = idx - d * TILE_T;             // consecutive tid -> consecutive t
        if (tt < tileLen)
            out[(size_t)d * nRealLen + t0 + tt] = sm[tt * ROWSTRIDE + d];
    }
}

extern "C" void kernel_launch(void* const* d_in, const int* in_sizes, int n_in,
                              void* d_out, int out_size)
{
    const float* TRFs = (const float*)d_in[0];
    const int*   sIdx = (const int*)d_in[1];
    // d_in[2] (nRealLen scalar) lives on device; derive shapes host-side instead:
    const int nSeq     = in_sizes[1];
    const int nWin     = in_sizes[0] / (nSeq * OUTD);
    const int nRealLen = out_size / OUTD;

    const int grid = (nRealLen + TILE_T - 1) / TILE_T;
    trf_fold_kernel<<<grid, NTHREADS>>>(TRFs, sIdx, (float*)d_out,
                                        nSeq, nWin, nRealLen);
}